// round 3
// baseline (speedup 1.0000x reference)
#include <cuda_runtime.h>
#include <math.h>

#define CC 48
#define TT 400
#define FF 129
#define BB 2
#define TFT 51600        // T*F
#define CTF 2476800      // C*T*F
#define BCTF 4953600     // B*C*T*F
#define OC 96
#define OUT_SZ 9907200   // B*OC*T*F
#define TILE_P 64
#define NBLK 807         // ceil(TFT/TILE_P)

// Scratch (allowed: __device__ globals, no allocation)
__device__ __align__(16) float g_Q[BCTF];
__device__ __align__(16) float g_K[BCTF];
__device__ __align__(16) float g_Kref[BCTF];
__device__ __align__(16) float g_ref[BCTF];

// ---------------------------------------------------------------------------
// Kernel 1: Q = pw1(dw1(x_mic)), K = pw2(dw2(Q)); dw folded into weights.
// ---------------------------------------------------------------------------
__global__ __launch_bounds__(256) void qk_kernel(
    const float* __restrict__ x,
    const float* __restrict__ dw1w, const float* __restrict__ dw1b,
    const float* __restrict__ pw1w, const float* __restrict__ pw1b,
    const float* __restrict__ dw2w, const float* __restrict__ dw2b,
    const float* __restrict__ pw2w, const float* __restrict__ pw2b)
{
    __shared__ __align__(16) float W1T[CC*CC];
    __shared__ __align__(16) float W2T[CC*CC];
    __shared__ __align__(16) float b1[CC];
    __shared__ __align__(16) float b2[CC];
    __shared__ __align__(16) float xs[CC][TILE_P];
    __shared__ __align__(16) float qs[CC][TILE_P];

    const int tid = threadIdx.x;
    const int b  = blockIdx.y;
    const int p0 = blockIdx.x * TILE_P;

    for (int i = tid; i < CC*CC; i += 256) {
        int o = i / CC, c = i % CC;
        W1T[c*CC+o] = pw1w[i] * dw1w[c];
        W2T[c*CC+o] = pw2w[i] * dw2w[c];
    }
    if (tid < CC) {
        float s1 = pw1b[tid], s2 = pw2b[tid];
        for (int c = 0; c < CC; c++) {
            s1 += pw1w[tid*CC+c] * dw1b[c];
            s2 += pw2w[tid*CC+c] * dw2b[c];
        }
        b1[tid] = s1; b2[tid] = s2;
    }
    for (int i = tid; i < CC*TILE_P; i += 256) {
        int c = i / TILE_P, p = i % TILE_P;
        int gp = p0 + p;
        xs[c][p] = (gp < TFT) ? x[(size_t)b*CTF + (size_t)c*TFT + gp] : 0.f;
    }
    __syncthreads();

    // Stage 1: Q
    for (int idx = tid; idx < (CC/4)*TILE_P; idx += 256) {
        int ot = idx / TILE_P, p = idx % TILE_P;
        int o0 = ot * 4;
        float4 acc = *(const float4*)&b1[o0];
        #pragma unroll
        for (int c = 0; c < CC; c++) {
            float4 w = *(const float4*)&W1T[c*CC+o0];
            float xv = xs[c][p];
            acc.x += w.x*xv; acc.y += w.y*xv; acc.z += w.z*xv; acc.w += w.w*xv;
        }
        qs[o0+0][p] = acc.x; qs[o0+1][p] = acc.y;
        qs[o0+2][p] = acc.z; qs[o0+3][p] = acc.w;
        int gp = p0 + p;
        if (gp < TFT) {
            size_t base = (size_t)b*CTF + gp;
            g_Q[base + (size_t)(o0+0)*TFT] = acc.x;
            g_Q[base + (size_t)(o0+1)*TFT] = acc.y;
            g_Q[base + (size_t)(o0+2)*TFT] = acc.z;
            g_Q[base + (size_t)(o0+3)*TFT] = acc.w;
        }
    }
    __syncthreads();

    // Stage 2: K from Q tile in smem
    for (int idx = tid; idx < (CC/4)*TILE_P; idx += 256) {
        int ot = idx / TILE_P, p = idx % TILE_P;
        int o0 = ot * 4;
        float4 acc = *(const float4*)&b2[o0];
        #pragma unroll
        for (int c = 0; c < CC; c++) {
            float4 w = *(const float4*)&W2T[c*CC+o0];
            float xv = qs[c][p];
            acc.x += w.x*xv; acc.y += w.y*xv; acc.z += w.z*xv; acc.w += w.w*xv;
        }
        int gp = p0 + p;
        if (gp < TFT) {
            size_t base = (size_t)b*CTF + gp;
            g_K[base + (size_t)(o0+0)*TFT] = acc.x;
            g_K[base + (size_t)(o0+1)*TFT] = acc.y;
            g_K[base + (size_t)(o0+2)*TFT] = acc.z;
            g_K[base + (size_t)(o0+3)*TFT] = acc.w;
        }
    }
}

// ---------------------------------------------------------------------------
// Kernel 2: K_ref = pw3(dw3(x_ref))
// ---------------------------------------------------------------------------
__global__ __launch_bounds__(256) void kref_kernel(
    const float* __restrict__ x,
    const float* __restrict__ dww, const float* __restrict__ dwb,
    const float* __restrict__ pww, const float* __restrict__ pwb)
{
    __shared__ __align__(16) float WT[CC*CC];
    __shared__ __align__(16) float bs[CC];
    __shared__ __align__(16) float xs[CC][TILE_P];

    const int tid = threadIdx.x;
    const int b  = blockIdx.y;
    const int p0 = blockIdx.x * TILE_P;

    for (int i = tid; i < CC*CC; i += 256) {
        int o = i / CC, c = i % CC;
        WT[c*CC+o] = pww[i] * dww[c];
    }
    if (tid < CC) {
        float s = pwb[tid];
        for (int c = 0; c < CC; c++) s += pww[tid*CC+c] * dwb[c];
        bs[tid] = s;
    }
    for (int i = tid; i < CC*TILE_P; i += 256) {
        int c = i / TILE_P, p = i % TILE_P;
        int gp = p0 + p;
        xs[c][p] = (gp < TFT) ? x[(size_t)b*CTF + (size_t)c*TFT + gp] : 0.f;
    }
    __syncthreads();

    for (int idx = tid; idx < (CC/4)*TILE_P; idx += 256) {
        int ot = idx / TILE_P, p = idx % TILE_P;
        int o0 = ot * 4;
        float4 acc = *(const float4*)&bs[o0];
        #pragma unroll
        for (int c = 0; c < CC; c++) {
            float4 w = *(const float4*)&WT[c*CC+o0];
            float xv = xs[c][p];
            acc.x += w.x*xv; acc.y += w.y*xv; acc.z += w.z*xv; acc.w += w.w*xv;
        }
        int gp = p0 + p;
        if (gp < TFT) {
            size_t base = (size_t)b*CTF + gp;
            g_Kref[base + (size_t)(o0+0)*TFT] = acc.x;
            g_Kref[base + (size_t)(o0+1)*TFT] = acc.y;
            g_Kref[base + (size_t)(o0+2)*TFT] = acc.z;
            g_Kref[base + (size_t)(o0+3)*TFT] = acc.w;
        }
    }
}

// ---------------------------------------------------------------------------
// Kernel 3: per-(b,t) frequency attention: S = Q^T K / sqrt(48),
//           A = softmax_g(S), mic_out = A @ x_mic^T. All in smem.
// ---------------------------------------------------------------------------
#define FP 132                               // padded F (multiple of 4)
#define SMEM_ATTN ((3*CC*FP + FP*FP)*4)      // 145,728 B

__global__ __launch_bounds__(256) void mic_attn_kernel(
    const float* __restrict__ x_mic, float* __restrict__ mic_out)
{
    extern __shared__ __align__(16) float sm[];
    float* Qs = sm;
    float* Ks = Qs + CC*FP;
    float* Xs = Ks + CC*FP;
    float* As = Xs + CC*FP;    // FP x FP

    const int tid = threadIdx.x;
    const int t = blockIdx.x, b = blockIdx.y;
    const size_t rbase = (size_t)b*CTF + (size_t)t*FF;

    for (int i = tid; i < CC*FP; i += 256) {
        int c = i / FP, f = i % FP;
        bool ok = f < FF;
        size_t gi = rbase + (size_t)c*TFT + f;
        Qs[i] = ok ? g_Q[gi]   : 0.f;
        Ks[i] = ok ? g_K[gi]   : 0.f;
        Xs[i] = ok ? x_mic[gi] : 0.f;
    }
    __syncthreads();

    // scores (raw, scale applied in softmax); zero-padded K cols -> As[:,129..131]=0
    for (int tile = tid; tile < 33*33; tile += 256) {
        int ft = tile / 33, gt = tile % 33;
        int f0 = ft*4, g0 = gt*4;
        float a00=0,a01=0,a02=0,a03=0, a10=0,a11=0,a12=0,a13=0;
        float a20=0,a21=0,a22=0,a23=0, a30=0,a31=0,a32=0,a33=0;
        #pragma unroll 4
        for (int c = 0; c < CC; c++) {
            float4 q = *(const float4*)&Qs[c*FP + f0];
            float4 k = *(const float4*)&Ks[c*FP + g0];
            a00 += q.x*k.x; a01 += q.x*k.y; a02 += q.x*k.z; a03 += q.x*k.w;
            a10 += q.y*k.x; a11 += q.y*k.y; a12 += q.y*k.z; a13 += q.y*k.w;
            a20 += q.z*k.x; a21 += q.z*k.y; a22 += q.z*k.z; a23 += q.z*k.w;
            a30 += q.w*k.x; a31 += q.w*k.y; a32 += q.w*k.z; a33 += q.w*k.w;
        }
        float* r0 = &As[(f0+0)*FP + g0];
        float* r1 = &As[(f0+1)*FP + g0];
        float* r2 = &As[(f0+2)*FP + g0];
        float* r3 = &As[(f0+3)*FP + g0];
        r0[0]=a00; r0[1]=a01; r0[2]=a02; r0[3]=a03;
        r1[0]=a10; r1[1]=a11; r1[2]=a12; r1[3]=a13;
        r2[0]=a20; r2[1]=a21; r2[2]=a22; r2[3]=a23;
        r3[0]=a30; r3[1]=a31; r3[2]=a32; r3[3]=a33;
    }
    __syncthreads();

    // row softmax over g (only rows f<129, cols g<129; padded cols stay 0)
    const float rs = 0.14433756729740643f; // 1/sqrt(48)
    const int warp = tid >> 5, lane = tid & 31;
    for (int f = warp; f < FF; f += 8) {
        float v[5]; float m = -1e30f;
        #pragma unroll
        for (int k = 0; k < 5; k++) {
            int g = lane + 32*k;
            v[k] = (g < FF) ? As[f*FP+g]*rs : -1e30f;
            m = fmaxf(m, v[k]);
        }
        #pragma unroll
        for (int off = 16; off; off >>= 1) m = fmaxf(m, __shfl_xor_sync(0xffffffffu, m, off));
        float e[5]; float s = 0.f;
        #pragma unroll
        for (int k = 0; k < 5; k++) {
            int g = lane + 32*k;
            e[k] = (g < FF) ? __expf(v[k]-m) : 0.f;
            s += e[k];
        }
        #pragma unroll
        for (int off = 16; off; off >>= 1) s += __shfl_xor_sync(0xffffffffu, s, off);
        float inv = 1.f/s;
        #pragma unroll
        for (int k = 0; k < 5; k++) {
            int g = lane + 32*k;
            if (g < FF) As[f*FP+g] = e[k]*inv;
        }
    }
    __syncthreads();

    // mic_out[c][f] = sum_g A[f][g] * X[c][g]
    for (int tile = tid; tile < 12*33; tile += 256) {
        int ct = tile / 33, ft = tile % 33;
        int c0 = ct*4, f0 = ft*4;
        float acc[4][4] = {};
        for (int g0 = 0; g0 < FP; g0 += 4) {
            float4 xv0 = *(const float4*)&Xs[(c0+0)*FP+g0];
            float4 xv1 = *(const float4*)&Xs[(c0+1)*FP+g0];
            float4 xv2 = *(const float4*)&Xs[(c0+2)*FP+g0];
            float4 xv3 = *(const float4*)&Xs[(c0+3)*FP+g0];
            float4 av0 = *(const float4*)&As[(f0+0)*FP+g0];
            float4 av1 = *(const float4*)&As[(f0+1)*FP+g0];
            float4 av2 = *(const float4*)&As[(f0+2)*FP+g0];
            float4 av3 = *(const float4*)&As[(f0+3)*FP+g0];
            acc[0][0] += xv0.x*av0.x + xv0.y*av0.y + xv0.z*av0.z + xv0.w*av0.w;
            acc[0][1] += xv0.x*av1.x + xv0.y*av1.y + xv0.z*av1.z + xv0.w*av1.w;
            acc[0][2] += xv0.x*av2.x + xv0.y*av2.y + xv0.z*av2.z + xv0.w*av2.w;
            acc[0][3] += xv0.x*av3.x + xv0.y*av3.y + xv0.z*av3.z + xv0.w*av3.w;
            acc[1][0] += xv1.x*av0.x + xv1.y*av0.y + xv1.z*av0.z + xv1.w*av0.w;
            acc[1][1] += xv1.x*av1.x + xv1.y*av1.y + xv1.z*av1.z + xv1.w*av1.w;
            acc[1][2] += xv1.x*av2.x + xv1.y*av2.y + xv1.z*av2.z + xv1.w*av2.w;
            acc[1][3] += xv1.x*av3.x + xv1.y*av3.y + xv1.z*av3.z + xv1.w*av3.w;
            acc[2][0] += xv2.x*av0.x + xv2.y*av0.y + xv2.z*av0.z + xv2.w*av0.w;
            acc[2][1] += xv2.x*av1.x + xv2.y*av1.y + xv2.z*av1.z + xv2.w*av1.w;
            acc[2][2] += xv2.x*av2.x + xv2.y*av2.y + xv2.z*av2.z + xv2.w*av2.w;
            acc[2][3] += xv2.x*av3.x + xv2.y*av3.y + xv2.z*av3.z + xv2.w*av3.w;
            acc[3][0] += xv3.x*av0.x + xv3.y*av0.y + xv3.z*av0.z + xv3.w*av0.w;
            acc[3][1] += xv3.x*av1.x + xv3.y*av1.y + xv3.z*av1.z + xv3.w*av1.w;
            acc[3][2] += xv3.x*av2.x + xv3.y*av2.y + xv3.z*av2.z + xv3.w*av2.w;
            acc[3][3] += xv3.x*av3.x + xv3.y*av3.y + xv3.z*av3.z + xv3.w*av3.w;
        }
        #pragma unroll
        for (int i = 0; i < 4; i++)
            #pragma unroll
            for (int j = 0; j < 4; j++) {
                int f = f0 + j;
                if (f < FF)
                    mic_out[rbase + (size_t)(c0+i)*TFT + f] = acc[i][j];
            }
    }
}

// ---------------------------------------------------------------------------
// Kernel 4: sliding-window ref attention. 8 t's per block share smem window.
// ref_out[b,c,t,f] = sum_j x_ref[b,c,t-10+j,f] * softmax_f(Q*K_ref[t-10+j])
// ---------------------------------------------------------------------------
__global__ __launch_bounds__(256) void ref_attn_kernel(const float* __restrict__ x_ref)
{
    __shared__ __align__(16) float krs[18*FP];
    __shared__ __align__(16) float xrs[18*FP];

    const int tid = threadIdx.x;
    const int t0 = blockIdx.x * 8;
    const int h = blockIdx.y, b = blockIdx.z;
    const size_t base = (size_t)b*CTF + (size_t)h*TFT;

    for (int i = tid; i < 18*FP; i += 256) {
        int r = i / FP, f = i % FP;
        int tk = t0 - 10 + r;
        bool ok = (tk >= 0) && (f < FF);
        size_t gi = base + (size_t)tk*FF + f;
        krs[i] = ok ? g_Kref[gi] : 0.f;
        xrs[i] = ok ? x_ref[gi]  : 0.f;
    }
    __syncthreads();

    const int w = tid >> 5, lane = tid & 31;
    const int t = t0 + w;
    const size_t qbase = base + (size_t)t*FF;

    float qv[5], acc[5];
    bool val[5];
    #pragma unroll
    for (int k = 0; k < 5; k++) {
        int f = lane + 32*k;
        val[k] = f < FF;
        qv[k] = val[k] ? g_Q[qbase + f] : 0.f;
        acc[k] = 0.f;
    }

    for (int j = 0; j < 11; j++) {
        int tk = t - 10 + j;
        if (tk < 0) continue;           // padded rows contribute exactly 0
        int r = w + j;
        float p[5]; float m = -1e30f;
        #pragma unroll
        for (int k = 0; k < 5; k++) {
            int f = lane + 32*k;
            p[k] = val[k] ? qv[k]*krs[r*FP+f] : -1e30f;
            m = fmaxf(m, p[k]);
        }
        #pragma unroll
        for (int off = 16; off; off >>= 1) m = fmaxf(m, __shfl_xor_sync(0xffffffffu, m, off));
        float e[5]; float s = 0.f;
        #pragma unroll
        for (int k = 0; k < 5; k++) {
            e[k] = val[k] ? __expf(p[k]-m) : 0.f;
            s += e[k];
        }
        #pragma unroll
        for (int off = 16; off; off >>= 1) s += __shfl_xor_sync(0xffffffffu, s, off);
        float inv = 1.f/s;
        #pragma unroll
        for (int k = 0; k < 5; k++) {
            int f = lane + 32*k;
            if (val[k]) acc[k] += xrs[r*FP+f] * e[k] * inv;
        }
    }
    #pragma unroll
    for (int k = 0; k < 5; k++) {
        int f = lane + 32*k;
        if (val[k]) g_ref[qbase + f] = acc[k];
    }
}

// ---------------------------------------------------------------------------
// Kernel 5: fusion 96x96 GEMM + folded BN + PReLU
// ---------------------------------------------------------------------------
#define SMEM_FUS ((OC*OC + 2*OC + OC*TILE_P)*4)   // 62,976 B

__global__ __launch_bounds__(256) void fusion_kernel(
    const float* __restrict__ fw, const float* __restrict__ fb,
    const float* __restrict__ gamma, const float* __restrict__ beta,
    const float* __restrict__ mean, const float* __restrict__ var,
    const float* __restrict__ prelu_a,
    const float* __restrict__ micp,
    float* __restrict__ outp)
{
    extern __shared__ __align__(16) float sm[];
    float* WT    = sm;              // OC*OC (transposed, BN-folded)
    float* bias  = WT + OC*OC;      // OC
    float* alpha = bias + OC;       // OC
    float* comb  = alpha + OC;      // OC * TILE_P

    const int tid = threadIdx.x;
    const int b  = blockIdx.y;
    const int p0 = blockIdx.x * TILE_P;

    if (tid < OC) {
        float a = gamma[tid] * rsqrtf(var[tid] + 1e-5f);
        alpha[tid] = a;
        bias[tid] = (fb[tid] - mean[tid]) * a + beta[tid];
    }
    __syncthreads();
    for (int i = tid; i < OC*OC; i += 256) {
        int o = i / OC, c = i % OC;
        WT[c*OC+o] = fw[i] * alpha[o];
    }
    for (int i = tid; i < OC*TILE_P; i += 256) {
        int c = i / TILE_P, p = i % TILE_P;
        int gp = p0 + p;
        float v = 0.f;
        if (gp < TFT) {
            if (c < CC) v = micp[(size_t)b*CTF + (size_t)c*TFT + gp];
            else        v = g_ref[(size_t)b*CTF + (size_t)(c-CC)*TFT + gp];
        }
        comb[i] = v;
    }
    __syncthreads();

    const float pa = prelu_a[0];
    for (int idx = tid; idx < (OC/4)*TILE_P; idx += 256) {
        int ot = idx / TILE_P, p = idx % TILE_P;
        int o0 = ot * 4;
        float4 acc = *(const float4*)&bias[o0];
        #pragma unroll 8
        for (int c = 0; c < OC; c++) {
            float4 wv = *(const float4*)&WT[c*OC+o0];
            float xv = comb[c*TILE_P + p];
            acc.x += wv.x*xv; acc.y += wv.y*xv; acc.z += wv.z*xv; acc.w += wv.w*xv;
        }
        int gp = p0 + p;
        if (gp < TFT) {
            size_t ob = (size_t)b*OC*TFT + gp;
            float y;
            y = acc.x; outp[ob + (size_t)(o0+0)*TFT] = (y >= 0.f) ? y : pa*y;
            y = acc.y; outp[ob + (size_t)(o0+1)*TFT] = (y >= 0.f) ? y : pa*y;
            y = acc.z; outp[ob + (size_t)(o0+2)*TFT] = (y >= 0.f) ? y : pa*y;
            y = acc.w; outp[ob + (size_t)(o0+3)*TFT] = (y >= 0.f) ? y : pa*y;
        }
    }
}

// ---------------------------------------------------------------------------
extern "C" void kernel_launch(void* const* d_in, const int* in_sizes, int n_in,
                              void* d_out, int out_size)
{
    const float* x_mic = (const float*)d_in[0];
    const float* x_ref = (const float*)d_in[1];
    const float* dw1w = (const float*)d_in[2];
    const float* dw1b = (const float*)d_in[3];
    const float* pw1w = (const float*)d_in[4];
    const float* pw1b = (const float*)d_in[5];
    const float* dw2w = (const float*)d_in[6];
    const float* dw2b = (const float*)d_in[7];
    const float* pw2w = (const float*)d_in[8];
    const float* pw2b = (const float*)d_in[9];
    const float* dw3w = (const float*)d_in[10];
    const float* dw3b = (const float*)d_in[11];
    const float* pw3w = (const float*)d_in[12];
    const float* pw3b = (const float*)d_in[13];
    const float* fw   = (const float*)d_in[14];
    const float* fb   = (const float*)d_in[15];
    const float* gam  = (const float*)d_in[16];
    const float* bet  = (const float*)d_in[17];
    const float* mea  = (const float*)d_in[18];
    const float* var  = (const float*)d_in[19];
    const float* pa   = (const float*)d_in[20];

    float* outp = (float*)d_out;
    float* micp = outp + OUT_SZ;    // second tuple output region

    cudaFuncSetAttribute(mic_attn_kernel,
                         cudaFuncAttributeMaxDynamicSharedMemorySize, SMEM_ATTN);
    cudaFuncSetAttribute(fusion_kernel,
                         cudaFuncAttributeMaxDynamicSharedMemorySize, SMEM_FUS);

    dim3 gpw(NBLK, BB);
    qk_kernel<<<gpw, 256>>>(x_mic, dw1w, dw1b, pw1w, pw1b, dw2w, dw2b, pw2w, pw2b);
    kref_kernel<<<gpw, 256>>>(x_ref, dw3w, dw3b, pw3w, pw3b);
    mic_attn_kernel<<<dim3(TT, BB), 256, SMEM_ATTN>>>(x_mic, micp);
    ref_attn_kernel<<<dim3(TT/8, CC, BB), 256>>>(x_ref);
    fusion_kernel<<<gpw, 256, SMEM_FUS>>>(fw, fb, gam, bet, mea, var, pa, micp, outp);
}

// round 5
// speedup vs baseline: 1.3080x; 1.3080x over previous
#include <cuda_runtime.h>
#include <math.h>

#define CC 48
#define TT 400
#define FF 129
#define BB 2
#define TFT 51600        // T*F
#define CTF 2476800      // C*T*F
#define BCTF 4953600     // B*C*T*F
#define OC 96
#define OUT_SZ 9907200   // B*OC*T*F

// Scratch (allowed: __device__ globals, no allocation)
__device__ __align__(16) float g_Q[BCTF];
__device__ __align__(16) float g_K[BCTF];
__device__ __align__(16) float g_Kref[BCTF];
__device__ __align__(16) float g_ref[BCTF];

// ===========================================================================
// Kernel 1 (merged): z=0 -> Q = pw1(dw1(x_mic)), K = pw2(dw2(Q))
//                    z=1 -> K_ref = pw3(dw3(x_ref))
// 4x4 register tiles; weight loads broadcast, activation loads conflict-free.
// ===========================================================================
#define PW_P 128
#define PW_NB 404        // ceil(51600/128)
#define SMEM_PW ((2*CC*CC + 2*CC + 2*CC*PW_P)*4)   // 67,968 B

__global__ __launch_bounds__(384) void pw_kernel(
    const float* __restrict__ x_mic, const float* __restrict__ x_ref,
    const float* __restrict__ dw1w, const float* __restrict__ dw1b,
    const float* __restrict__ pw1w, const float* __restrict__ pw1b,
    const float* __restrict__ dw2w, const float* __restrict__ dw2b,
    const float* __restrict__ pw2w, const float* __restrict__ pw2b,
    const float* __restrict__ dw3w, const float* __restrict__ dw3b,
    const float* __restrict__ pw3w, const float* __restrict__ pw3b)
{
    extern __shared__ float smp[];
    float* W1T = smp;                  // CC*CC
    float* W2T = W1T + CC*CC;          // CC*CC
    float* bb1 = W2T + CC*CC;          // CC
    float* bb2 = bb1 + CC;             // CC
    float* xs  = bb2 + CC;             // CC*PW_P
    float* qs  = xs + CC*PW_P;         // CC*PW_P

    const int tid = threadIdx.x;
    const int b = blockIdx.y, job = blockIdx.z;
    const int p0 = blockIdx.x * PW_P;
    const float* x   = job ? x_ref : x_mic;
    const float* w1  = job ? pw3w : pw1w;
    const float* d1w = job ? dw3w : dw1w;
    const float* p1b = job ? pw3b : pw1b;
    const float* d1b = job ? dw3b : dw1b;

    for (int i = tid; i < CC*CC; i += 384) {
        int o = i / CC, c = i % CC;
        W1T[c*CC+o] = w1[i] * d1w[c];
        if (!job) W2T[c*CC+o] = pw2w[i] * dw2w[c];
    }
    if (tid < CC) {
        float s1 = p1b[tid];
        for (int c = 0; c < CC; c++) s1 += w1[tid*CC+c] * d1b[c];
        bb1[tid] = s1;
        if (!job) {
            float s2 = pw2b[tid];
            for (int c = 0; c < CC; c++) s2 += pw2w[tid*CC+c] * dw2b[c];
            bb2[tid] = s2;
        }
    }
    for (int i = tid; i < CC*PW_P; i += 384) {
        int c = i / PW_P, p = i % PW_P;
        int gp = p0 + p;
        xs[i] = (gp < TFT) ? x[(size_t)b*CTF + (size_t)c*TFT + gp] : 0.f;
    }
    __syncthreads();

    const int ot = tid >> 5, pt = tid & 31;   // 12 o-tiles x 32 p-tiles
    const int o0 = ot*4, pp = pt*4;
    const int gp0 = p0 + pp;
    float* out1 = job ? g_Kref : g_Q;

    // stage 1
    {
        float4 a0={0,0,0,0},a1={0,0,0,0},a2={0,0,0,0},a3={0,0,0,0};
        #pragma unroll 4
        for (int c = 0; c < CC; c++) {
            float4 w  = *(const float4*)&W1T[c*CC+o0];
            float4 xv = *(const float4*)&xs[c*PW_P+pp];
            a0.x+=w.x*xv.x; a0.y+=w.x*xv.y; a0.z+=w.x*xv.z; a0.w+=w.x*xv.w;
            a1.x+=w.y*xv.x; a1.y+=w.y*xv.y; a1.z+=w.y*xv.z; a1.w+=w.y*xv.w;
            a2.x+=w.z*xv.x; a2.y+=w.z*xv.y; a2.z+=w.z*xv.z; a2.w+=w.z*xv.w;
            a3.x+=w.w*xv.x; a3.y+=w.w*xv.y; a3.z+=w.w*xv.z; a3.w+=w.w*xv.w;
        }
        float4 bv = *(const float4*)&bb1[o0];
        a0.x+=bv.x; a0.y+=bv.x; a0.z+=bv.x; a0.w+=bv.x;
        a1.x+=bv.y; a1.y+=bv.y; a1.z+=bv.y; a1.w+=bv.y;
        a2.x+=bv.z; a2.y+=bv.z; a2.z+=bv.z; a2.w+=bv.z;
        a3.x+=bv.w; a3.y+=bv.w; a3.z+=bv.w; a3.w+=bv.w;
        if (!job) {
            *(float4*)&qs[(o0+0)*PW_P+pp] = a0;
            *(float4*)&qs[(o0+1)*PW_P+pp] = a1;
            *(float4*)&qs[(o0+2)*PW_P+pp] = a2;
            *(float4*)&qs[(o0+3)*PW_P+pp] = a3;
        }
        if (gp0 < TFT) {
            size_t base = (size_t)b*CTF + gp0;
            *(float4*)&out1[base + (size_t)(o0+0)*TFT] = a0;
            *(float4*)&out1[base + (size_t)(o0+1)*TFT] = a1;
            *(float4*)&out1[base + (size_t)(o0+2)*TFT] = a2;
            *(float4*)&out1[base + (size_t)(o0+3)*TFT] = a3;
        }
    }
    if (job) return;
    __syncthreads();

    // stage 2: K from Q tile in smem
    {
        float4 a0={0,0,0,0},a1={0,0,0,0},a2={0,0,0,0},a3={0,0,0,0};
        #pragma unroll 4
        for (int c = 0; c < CC; c++) {
            float4 w  = *(const float4*)&W2T[c*CC+o0];
            float4 xv = *(const float4*)&qs[c*PW_P+pp];
            a0.x+=w.x*xv.x; a0.y+=w.x*xv.y; a0.z+=w.x*xv.z; a0.w+=w.x*xv.w;
            a1.x+=w.y*xv.x; a1.y+=w.y*xv.y; a1.z+=w.y*xv.z; a1.w+=w.y*xv.w;
            a2.x+=w.z*xv.x; a2.y+=w.z*xv.y; a2.z+=w.z*xv.z; a2.w+=w.z*xv.w;
            a3.x+=w.w*xv.x; a3.y+=w.w*xv.y; a3.z+=w.w*xv.z; a3.w+=w.w*xv.w;
        }
        float4 bv = *(const float4*)&bb2[o0];
        a0.x+=bv.x; a0.y+=bv.x; a0.z+=bv.x; a0.w+=bv.x;
        a1.x+=bv.y; a1.y+=bv.y; a1.z+=bv.y; a1.w+=bv.y;
        a2.x+=bv.z; a2.y+=bv.z; a2.z+=bv.z; a2.w+=bv.z;
        a3.x+=bv.w; a3.y+=bv.w; a3.z+=bv.w; a3.w+=bv.w;
        if (gp0 < TFT) {
            size_t base = (size_t)b*CTF + gp0;
            *(float4*)&g_K[base + (size_t)(o0+0)*TFT] = a0;
            *(float4*)&g_K[base + (size_t)(o0+1)*TFT] = a1;
            *(float4*)&g_K[base + (size_t)(o0+2)*TFT] = a2;
            *(float4*)&g_K[base + (size_t)(o0+3)*TFT] = a3;
        }
    }
}

// ===========================================================================
// Kernel 2: mic attention per (b,t). Transposed A/X layouts -> all smem
// accesses lane-contiguous or broadcast (conflict-free by construction).
//   scores: 8g x 4f tiles -> A_T[g][f] (STS.128 lane-contiguous in f)
//   softmax: one thread per f-column, no shuffles; 1/sum deferred to AV
//   AV: 4c x 4f tiles, outer product over g (A_T contig, X_T broadcast)
// ===========================================================================
#define ATW 132          // A_T row stride (f), mult of 4
#define KSW 136          // Ks row stride / padded g rows, mult of 8
#define XTW 52           // X_T row stride (c)
#define SMEM_ATTN ((CC*ATW + CC*KSW + KSW*XTW + KSW*ATW + ATW)*4)  // 152,080 B

__global__ __launch_bounds__(288) void mic_attn_kernel(
    const float* __restrict__ x_mic, float* __restrict__ mic_out)
{
    extern __shared__ float sm[];
    float* Qs  = sm;                   // [CC][ATW]
    float* Ks  = Qs + CC*ATW;          // [CC][KSW]
    float* XT  = Ks + CC*KSW;          // [KSW][XTW]  (X transposed)
    float* AT  = XT + KSW*XTW;         // [KSW][ATW]  (A transposed: [g][f])
    float* SIv = AT + KSW*ATW;         // [ATW] 1/sum per f

    const int tid = threadIdx.x;
    const int t = blockIdx.x, b = blockIdx.y;
    const size_t rbase = (size_t)b*CTF + (size_t)t*FF;

    for (int i = tid; i < CC*ATW; i += 288) {
        int c = i / ATW, f = i % ATW;
        Qs[i] = (f < FF) ? g_Q[rbase + (size_t)c*TFT + f] : 0.f;
    }
    for (int i = tid; i < CC*KSW; i += 288) {
        int c = i / KSW, g = i % KSW;
        Ks[i] = (g < FF) ? g_K[rbase + (size_t)c*TFT + g] : 0.f;
    }
    for (int i = tid; i < CC*KSW; i += 288) {
        int c = i / KSW, g = i % KSW;
        XT[g*XTW + c] = (g < FF) ? x_mic[rbase + (size_t)c*TFT + g] : 0.f;
    }
    __syncthreads();

    // ---- scores: 17 g-tiles x 33 f-tiles = 561 tiles, write A_T raw ----
    for (int idx = tid; idx < 17*33; idx += 288) {
        int gt = idx / 33, ft = idx % 33;   // lanes vary ft -> f contiguous
        int g0 = gt*8, f0 = ft*4;
        float4 s0={0,0,0,0},s1={0,0,0,0},s2={0,0,0,0},s3={0,0,0,0};
        float4 s4={0,0,0,0},s5={0,0,0,0},s6={0,0,0,0},s7={0,0,0,0};
        #pragma unroll 4
        for (int c = 0; c < CC; c++) {
            float4 q  = *(const float4*)&Qs[c*ATW + f0];
            float4 k0 = *(const float4*)&Ks[c*KSW + g0];
            float4 k1 = *(const float4*)&Ks[c*KSW + g0 + 4];
            s0.x+=k0.x*q.x; s0.y+=k0.x*q.y; s0.z+=k0.x*q.z; s0.w+=k0.x*q.w;
            s1.x+=k0.y*q.x; s1.y+=k0.y*q.y; s1.z+=k0.y*q.z; s1.w+=k0.y*q.w;
            s2.x+=k0.z*q.x; s2.y+=k0.z*q.y; s2.z+=k0.z*q.z; s2.w+=k0.z*q.w;
            s3.x+=k0.w*q.x; s3.y+=k0.w*q.y; s3.z+=k0.w*q.z; s3.w+=k0.w*q.w;
            s4.x+=k1.x*q.x; s4.y+=k1.x*q.y; s4.z+=k1.x*q.z; s4.w+=k1.x*q.w;
            s5.x+=k1.y*q.x; s5.y+=k1.y*q.y; s5.z+=k1.y*q.z; s5.w+=k1.y*q.w;
            s6.x+=k1.z*q.x; s6.y+=k1.z*q.y; s6.z+=k1.z*q.z; s6.w+=k1.z*q.w;
            s7.x+=k1.w*q.x; s7.y+=k1.w*q.y; s7.z+=k1.w*q.z; s7.w+=k1.w*q.w;
        }
        *(float4*)&AT[(g0+0)*ATW + f0] = s0;
        *(float4*)&AT[(g0+1)*ATW + f0] = s1;
        *(float4*)&AT[(g0+2)*ATW + f0] = s2;
        *(float4*)&AT[(g0+3)*ATW + f0] = s3;
        *(float4*)&AT[(g0+4)*ATW + f0] = s4;
        *(float4*)&AT[(g0+5)*ATW + f0] = s5;
        *(float4*)&AT[(g0+6)*ATW + f0] = s6;
        *(float4*)&AT[(g0+7)*ATW + f0] = s7;
    }
    __syncthreads();

    // ---- softmax over g per f-column; scores tiny -> no max shift needed ----
    if (tid < ATW) {
        const int f = tid;
        const float rs = 0.14433756729740643f;   // 1/sqrt(48)
        float a0=0.f, a1=0.f, a2=0.f, a3=0.f;
        for (int g = 0; g < 128; g += 4) {
            float e0 = __expf(AT[(g+0)*ATW+f]*rs);
            float e1 = __expf(AT[(g+1)*ATW+f]*rs);
            float e2 = __expf(AT[(g+2)*ATW+f]*rs);
            float e3 = __expf(AT[(g+3)*ATW+f]*rs);
            AT[(g+0)*ATW+f] = e0; AT[(g+1)*ATW+f] = e1;
            AT[(g+2)*ATW+f] = e2; AT[(g+3)*ATW+f] = e3;
            a0 += e0; a1 += e1; a2 += e2; a3 += e3;
        }
        float e = __expf(AT[128*ATW+f]*rs);
        AT[128*ATW+f] = e;
        SIv[f] = 1.f / (a0+a1+a2+a3+e);
    }
    __syncthreads();

    // ---- AV: 12 c-tiles x 33 f-tiles, outer product over g<129 ----
    for (int idx = tid; idx < 12*33; idx += 288) {
        int ct = idx / 33, ft = idx % 33;   // lanes vary ft
        int c0 = ct*4, f0 = ft*4;
        float4 a0={0,0,0,0},a1={0,0,0,0},a2={0,0,0,0},a3={0,0,0,0};
        #pragma unroll 3
        for (int g = 0; g < FF; g++) {
            float4 a  = *(const float4*)&AT[g*ATW + f0];
            float4 xv = *(const float4*)&XT[g*XTW + c0];
            a0.x+=xv.x*a.x; a0.y+=xv.x*a.y; a0.z+=xv.x*a.z; a0.w+=xv.x*a.w;
            a1.x+=xv.y*a.x; a1.y+=xv.y*a.y; a1.z+=xv.y*a.z; a1.w+=xv.y*a.w;
            a2.x+=xv.z*a.x; a2.y+=xv.z*a.y; a2.z+=xv.z*a.z; a2.w+=xv.z*a.w;
            a3.x+=xv.w*a.x; a3.y+=xv.w*a.y; a3.z+=xv.w*a.z; a3.w+=xv.w*a.w;
        }
        float4 iv = *(const float4*)&SIv[f0];
        float v[4][4] = {
            {a0.x*iv.x, a0.y*iv.y, a0.z*iv.z, a0.w*iv.w},
            {a1.x*iv.x, a1.y*iv.y, a1.z*iv.z, a1.w*iv.w},
            {a2.x*iv.x, a2.y*iv.y, a2.z*iv.z, a2.w*iv.w},
            {a3.x*iv.x, a3.y*iv.y, a3.z*iv.z, a3.w*iv.w}};
        #pragma unroll
        for (int i = 0; i < 4; i++) {
            size_t ob = rbase + (size_t)(c0+i)*TFT;
            #pragma unroll
            for (int j = 0; j < 4; j++) {
                int f = f0 + j;
                if (f < FF) mic_out[ob + f] = v[i][j];
            }
        }
    }
}

// ===========================================================================
// Kernel 3: sliding-window ref attention (no max-shift; scores are small).
// ===========================================================================
#define RFP 132

__global__ __launch_bounds__(256) void ref_attn_kernel(const float* __restrict__ x_ref)
{
    __shared__ __align__(16) float krs[18*RFP];
    __shared__ __align__(16) float xrs[18*RFP];

    const int tid = threadIdx.x;
    const int t0 = blockIdx.x * 8;
    const int h = blockIdx.y, b = blockIdx.z;
    const size_t base = (size_t)b*CTF + (size_t)h*TFT;

    for (int i = tid; i < 18*RFP; i += 256) {
        int r = i / RFP, f = i % RFP;
        int tk = t0 - 10 + r;
        bool ok = (tk >= 0) && (f < FF);
        size_t gi = base + (size_t)tk*FF + f;
        krs[i] = ok ? g_Kref[gi] : 0.f;
        xrs[i] = ok ? x_ref[gi]  : 0.f;
    }
    __syncthreads();

    const int w = tid >> 5, lane = tid & 31;
    const int t = t0 + w;
    const size_t qbase = base + (size_t)t*FF;

    float qv[5], acc[5];
    bool val[5];
    #pragma unroll
    for (int k = 0; k < 5; k++) {
        int f = lane + 32*k;
        val[k] = f < FF;
        qv[k] = val[k] ? g_Q[qbase + f] : 0.f;
        acc[k] = 0.f;
    }

    for (int j = 0; j < 11; j++) {
        int tk = t - 10 + j;
        if (tk < 0) continue;           // padded rows contribute exactly 0
        int r = w + j;
        float e[5]; float s = 0.f;
        float xv[5];
        #pragma unroll
        for (int k = 0; k < 5; k++) {
            int f = lane + 32*k;
            float kv = val[k] ? krs[r*RFP+f] : 0.f;
            xv[k]    = val[k] ? xrs[r*RFP+f] : 0.f;
            e[k] = val[k] ? __expf(qv[k]*kv) : 0.f;
            s += e[k];
        }
        #pragma unroll
        for (int off = 16; off; off >>= 1) s += __shfl_xor_sync(0xffffffffu, s, off);
        float inv = 1.f/s;
        #pragma unroll
        for (int k = 0; k < 5; k++)
            acc[k] += xv[k] * (e[k]*inv);
    }
    #pragma unroll
    for (int k = 0; k < 5; k++) {
        int f = lane + 32*k;
        if (val[k]) g_ref[qbase + f] = acc[k];
    }
}

// ===========================================================================
// Kernel 4: fusion 96x96 GEMM + folded BN + PReLU. 8-out x 4-p tiles.
// ===========================================================================
#define FUS_P 128
#define FUS_NB 404
#define SMEM_FUS ((OC*OC + 2*OC + OC*FUS_P)*4)   // 86,784 B

__global__ __launch_bounds__(384) void fusion_kernel(
    const float* __restrict__ fw, const float* __restrict__ fb,
    const float* __restrict__ gamma, const float* __restrict__ beta,
    const float* __restrict__ mean, const float* __restrict__ var,
    const float* __restrict__ prelu_a,
    const float* __restrict__ micp,
    float* __restrict__ outp)
{
    extern __shared__ float smf[];
    float* WT    = smf;             // OC*OC transposed, BN-folded
    float* bias  = WT + OC*OC;
    float* alpha = bias + OC;
    float* comb  = alpha + OC;      // OC*FUS_P

    const int tid = threadIdx.x;
    const int b  = blockIdx.y;
    const int p0 = blockIdx.x * FUS_P;

    if (tid < OC) {
        float a = gamma[tid] * rsqrtf(var[tid] + 1e-5f);
        alpha[tid] = a;
        bias[tid] = (fb[tid] - mean[tid]) * a + beta[tid];
    }
    __syncthreads();
    for (int i = tid; i < OC*OC; i += 384) {
        int o = i / OC, c = i % OC;
        WT[c*OC+o] = fw[i] * alpha[o];
    }
    for (int i = tid; i < OC*FUS_P; i += 384) {
        int c = i / FUS_P, p = i % FUS_P;
        int gp = p0 + p;
        float v = 0.f;
        if (gp < TFT) {
            if (c < CC) v = micp[(size_t)b*CTF + (size_t)c*TFT + gp];
            else        v = g_ref[(size_t)b*CTF + (size_t)(c-CC)*TFT + gp];
        }
        comb[i] = v;
    }
    __syncthreads();

    const float pa = prelu_a[0];
    const int ot = tid >> 5, pt = tid & 31;    // 12 o-tiles(8) x 32 p-tiles(4)
    const int o0 = ot*8, pp = pt*4;
    const int gp0 = p0 + pp;

    float4 acc[8] = {};
    #pragma unroll 4
    for (int c = 0; c < OC; c++) {
        float4 w0 = *(const float4*)&WT[c*OC + o0];
        float4 w1 = *(const float4*)&WT[c*OC + o0 + 4];
        float4 xv = *(const float4*)&comb[c*FUS_P + pp];
        acc[0].x+=w0.x*xv.x; acc[0].y+=w0.x*xv.y; acc[0].z+=w0.x*xv.z; acc[0].w+=w0.x*xv.w;
        acc[1].x+=w0.y*xv.x; acc[1].y+=w0.y*xv.y; acc[1].z+=w0.y*xv.z; acc[1].w+=w0.y*xv.w;
        acc[2].x+=w0.z*xv.x; acc[2].y+=w0.z*xv.y; acc[2].z+=w0.z*xv.z; acc[2].w+=w0.z*xv.w;
        acc[3].x+=w0.w*xv.x; acc[3].y+=w0.w*xv.y; acc[3].z+=w0.w*xv.z; acc[3].w+=w0.w*xv.w;
        acc[4].x+=w1.x*xv.x; acc[4].y+=w1.x*xv.y; acc[4].z+=w1.x*xv.z; acc[4].w+=w1.x*xv.w;
        acc[5].x+=w1.y*xv.x; acc[5].y+=w1.y*xv.y; acc[5].z+=w1.y*xv.z; acc[5].w+=w1.y*xv.w;
        acc[6].x+=w1.z*xv.x; acc[6].y+=w1.z*xv.y; acc[6].z+=w1.z*xv.z; acc[6].w+=w1.z*xv.w;
        acc[7].x+=w1.w*xv.x; acc[7].y+=w1.w*xv.y; acc[7].z+=w1.w*xv.z; acc[7].w+=w1.w*xv.w;
    }
    if (gp0 < TFT) {
        size_t ob = (size_t)b*OC*TFT + gp0;
        #pragma unroll
        for (int o = 0; o < 8; o++) {
            float bs = bias[o0+o];
            float4 y = acc[o];
            y.x += bs; y.y += bs; y.z += bs; y.w += bs;
            y.x = (y.x >= 0.f) ? y.x : pa*y.x;
            y.y = (y.y >= 0.f) ? y.y : pa*y.y;
            y.z = (y.z >= 0.f) ? y.z : pa*y.z;
            y.w = (y.w >= 0.f) ? y.w : pa*y.w;
            *(float4*)&outp[ob + (size_t)(o0+o)*TFT] = y;
        }
    }
}

// ---------------------------------------------------------------------------
extern "C" void kernel_launch(void* const* d_in, const int* in_sizes, int n_in,
                              void* d_out, int out_size)
{
    const float* x_mic = (const float*)d_in[0];
    const float* x_ref = (const float*)d_in[1];
    const float* dw1w = (const float*)d_in[2];
    const float* dw1b = (const float*)d_in[3];
    const float* pw1w = (const float*)d_in[4];
    const float* pw1b = (const float*)d_in[5];
    const float* dw2w = (const float*)d_in[6];
    const float* dw2b = (const float*)d_in[7];
    const float* pw2w = (const float*)d_in[8];
    const float* pw2b = (const float*)d_in[9];
    const float* dw3w = (const float*)d_in[10];
    const float* dw3b = (const float*)d_in[11];
    const float* pw3w = (const float*)d_in[12];
    const float* pw3b = (const float*)d_in[13];
    const float* fw   = (const float*)d_in[14];
    const float* fb   = (const float*)d_in[15];
    const float* gam  = (const float*)d_in[16];
    const float* bet  = (const float*)d_in[17];
    const float* mea  = (const float*)d_in[18];
    const float* var  = (const float*)d_in[19];
    const float* pa   = (const float*)d_in[20];

    float* outp = (float*)d_out;
    float* micp = outp + OUT_SZ;    // second tuple output region

    cudaFuncSetAttribute(pw_kernel,
                         cudaFuncAttributeMaxDynamicSharedMemorySize, SMEM_PW);
    cudaFuncSetAttribute(mic_attn_kernel,
                         cudaFuncAttributeMaxDynamicSharedMemorySize, SMEM_ATTN);
    cudaFuncSetAttribute(fusion_kernel,
                         cudaFuncAttributeMaxDynamicSharedMemorySize, SMEM_FUS);

    pw_kernel<<<dim3(PW_NB, BB, 2), 384, SMEM_PW>>>(
        x_mic, x_ref, dw1w, dw1b, pw1w, pw1b, dw2w, dw2b, pw2w, pw2b,
        dw3w, dw3b, pw3w, pw3b);
    mic_attn_kernel<<<dim3(TT, BB), 288, SMEM_ATTN>>>(x_mic, micp);
    ref_attn_kernel<<<dim3(TT/8, CC, BB), 256>>>(x_ref);
    fusion_kernel<<<dim3(FUS_NB, BB), 384, SMEM_FUS>>>(
        fw, fb, gam, bet, mea, var, pa, micp, outp);
}